// round 3
// baseline (speedup 1.0000x reference)
#include <cuda_runtime.h>

// QuadratureFunction: per-cell DOF gather (3 vertex + 3x2 edge w/ orientation
// flip + 1 face) contracted against y[C, NB=10, Q=16] -> out[C, Q=16].
//
// HBM-streaming bound: y (320MB) dominates. Mapping: 4 threads per cell,
// each handles 4 quadrature points via float4 (16B coalesced loads/stores).

#define NB 10
#define Q  16

__global__ void quad_kernel(const float* __restrict__ vertex_dofs,
                            const float* __restrict__ edge_dofs,
                            const float* __restrict__ face_dofs,
                            const float* __restrict__ y,
                            const int*   __restrict__ faces,
                            const int*   __restrict__ faces_to_edges,
                            const int*   __restrict__ edge_orientation,
                            float*       __restrict__ out,
                            int C)
{
    int t = blockIdx.x * blockDim.x + threadIdx.x;
    int c  = t >> 2;            // cell index (4 threads per cell)
    int q0 = (t & 3) << 2;      // starting quadrature point (0,4,8,12)
    if (c >= C) return;

    // --- gather local dofs (replicated across the 4 threads of a cell;
    //     identical addresses within a warp cost no extra transactions) ---
    float dofs[NB];

    int v0 = faces[3 * c + 0];
    int v1 = faces[3 * c + 1];
    int v2 = faces[3 * c + 2];
    dofs[0] = vertex_dofs[v0];   // DV = 1
    dofs[1] = vertex_dofs[v1];
    dofs[2] = vertex_dofs[v2];

    #pragma unroll
    for (int e = 0; e < 3; e++) {
        int ei = faces_to_edges[3 * c + e];
        int o  = edge_orientation[3 * c + e];
        // DE = 2: keep order when o==1, flip when o==0
        float d0 = edge_dofs[2 * ei + 0];
        float d1 = edge_dofs[2 * ei + 1];
        dofs[3 + 2 * e + 0] = o ? d0 : d1;
        dofs[3 + 2 * e + 1] = o ? d1 : d0;
    }

    dofs[9] = face_dofs[c];      // DF = 1

    // --- contraction: out[c, q0..q0+3] = sum_b dofs[b] * y[c, b, q0..q0+3] ---
    const float4* yb = reinterpret_cast<const float4*>(
        y + (size_t)c * (NB * Q) + q0);

    float4 acc = make_float4(0.f, 0.f, 0.f, 0.f);
    #pragma unroll
    for (int b = 0; b < NB; b++) {
        float4 yv = yb[b * (Q / 4)];
        acc.x = fmaf(dofs[b], yv.x, acc.x);
        acc.y = fmaf(dofs[b], yv.y, acc.y);
        acc.z = fmaf(dofs[b], yv.z, acc.z);
        acc.w = fmaf(dofs[b], yv.w, acc.w);
    }

    reinterpret_cast<float4*>(out + (size_t)c * Q + q0)[0] = acc;
}

extern "C" void kernel_launch(void* const* d_in, const int* in_sizes, int n_in,
                              void* d_out, int out_size)
{
    const float* vertex_dofs      = (const float*)d_in[0];
    const float* edge_dofs        = (const float*)d_in[1];
    const float* face_dofs        = (const float*)d_in[2];
    const float* y                = (const float*)d_in[3];
    const int*   faces            = (const int*)d_in[4];
    const int*   faces_to_edges   = (const int*)d_in[5];
    const int*   edge_orientation = (const int*)d_in[6];
    float*       out              = (float*)d_out;

    int C = in_sizes[2];               // face_dofs has C*DF = C elements
    int total_threads = C * 4;         // 4 threads per cell
    int block = 256;
    int grid = (total_threads + block - 1) / block;

    quad_kernel<<<grid, block>>>(vertex_dofs, edge_dofs, face_dofs, y,
                                 faces, faces_to_edges, edge_orientation,
                                 out, C);
}

// round 4
// speedup vs baseline: 1.1237x; 1.1237x over previous
#include <cuda_runtime.h>

// QuadratureFunction: per-cell DOF gather (3 vertex + 3x2 edge w/ orientation
// flip + 1 face) contracted against y[C, NB=10, Q=16] -> out[C, Q=16].
//
// HBM-streaming bound: y (320MB, streamed exactly once) dominates.
// Mapping: 4 threads per cell, each owns 4 quadrature points (float4).
// R4 change: streaming cache hints (__ldcs on y, __stcs on out) so the
// one-shot y stream doesn't evict the reusable vertex/edge dof arrays
// (7MB, each element reused 2-6x) from L2.

#define NB 10
#define Q  16

__global__ __launch_bounds__(512)
void quad_kernel(const float* __restrict__ vertex_dofs,
                 const float* __restrict__ edge_dofs,
                 const float* __restrict__ face_dofs,
                 const float* __restrict__ y,
                 const int*   __restrict__ faces,
                 const int*   __restrict__ faces_to_edges,
                 const int*   __restrict__ edge_orientation,
                 float*       __restrict__ out,
                 int C)
{
    int t = blockIdx.x * blockDim.x + threadIdx.x;
    int c  = t >> 2;            // cell index (4 threads per cell)
    int q0 = (t & 3) << 2;      // starting quadrature point (0,4,8,12)
    if (c >= C) return;

    // --- issue all 10 streaming y loads up front (max MLP) ---
    const float4* yb = reinterpret_cast<const float4*>(
        y + (size_t)c * (NB * Q) + q0);

    float4 yv[NB];
    #pragma unroll
    for (int b = 0; b < NB; b++)
        yv[b] = __ldcs(&yb[b * (Q / 4)]);   // evict-first: no L2 pollution

    // --- gather local dofs (replicated across the 4 threads of a cell;
    //     identical addresses within a warp coalesce to one transaction).
    //     These stay default-cached: they are the L2-resident working set. ---
    float dofs[NB];

    int v0 = faces[3 * c + 0];
    int v1 = faces[3 * c + 1];
    int v2 = faces[3 * c + 2];
    dofs[0] = vertex_dofs[v0];   // DV = 1
    dofs[1] = vertex_dofs[v1];
    dofs[2] = vertex_dofs[v2];

    #pragma unroll
    for (int e = 0; e < 3; e++) {
        int ei = faces_to_edges[3 * c + e];
        int o  = edge_orientation[3 * c + e];
        // DE = 2: keep order when o==1, flip when o==0
        float d0 = edge_dofs[2 * ei + 0];
        float d1 = edge_dofs[2 * ei + 1];
        dofs[3 + 2 * e + 0] = o ? d0 : d1;
        dofs[3 + 2 * e + 1] = o ? d1 : d0;
    }

    dofs[9] = face_dofs[c];      // DF = 1

    // --- contraction: out[c, q0..q0+3] = sum_b dofs[b] * y[c, b, q0..q0+3] ---
    float4 acc = make_float4(0.f, 0.f, 0.f, 0.f);
    #pragma unroll
    for (int b = 0; b < NB; b++) {
        acc.x = fmaf(dofs[b], yv[b].x, acc.x);
        acc.y = fmaf(dofs[b], yv[b].y, acc.y);
        acc.z = fmaf(dofs[b], yv[b].z, acc.z);
        acc.w = fmaf(dofs[b], yv[b].w, acc.w);
    }

    __stcs(reinterpret_cast<float4*>(out + (size_t)c * Q + q0), acc);
}

extern "C" void kernel_launch(void* const* d_in, const int* in_sizes, int n_in,
                              void* d_out, int out_size)
{
    const float* vertex_dofs      = (const float*)d_in[0];
    const float* edge_dofs        = (const float*)d_in[1];
    const float* face_dofs        = (const float*)d_in[2];
    const float* y                = (const float*)d_in[3];
    const int*   faces            = (const int*)d_in[4];
    const int*   faces_to_edges   = (const int*)d_in[5];
    const int*   edge_orientation = (const int*)d_in[6];
    float*       out              = (float*)d_out;

    int C = in_sizes[2];               // face_dofs has C*DF = C elements
    int total_threads = C * 4;         // 4 threads per cell
    int block = 512;
    int grid = (total_threads + block - 1) / block;

    quad_kernel<<<grid, block>>>(vertex_dofs, edge_dofs, face_dofs, y,
                                 faces, faces_to_edges, edge_orientation,
                                 out, C);
}